// round 15
// baseline (speedup 1.0000x reference)
#include <cuda_runtime.h>
#include <cuda_fp16.h>
#include <cstdint>

#define UNITS 512
#define N_DOP 128
#define N_INPUT 512
#define MAX_B 65536
#define MAX_TILES (MAX_B / 128)

#define BM 128
#define BN 128
#define BK 64
#define THREADS 256
#define KSTAGES (N_INPUT / BK)   // 8

// dynamic smem: 3-stage ring of {A 16K | B 16K}
#define NBUF 3
#define BUF_STRIDE 32768
#define OFF_A 0
#define OFF_B 16384
#define SMEM_DYN (NBUF * BUF_STRIDE + 128)

__device__ float g_mult[UNITS];
__device__ float g_fac[N_DOP];
__device__ int   g_act[N_DOP];
__device__ int   g_tilecnt[MAX_TILES];
__device__ __half g_w16[UNITS * N_INPUT];          // [n][k] = w[k][n] * mult[n]
__device__ __half g_x16[(size_t)MAX_B * N_INPUT];  // fp16 copy of X

__device__ __forceinline__ uint32_t smem_u32(const void* p) {
    uint32_t a;
    asm("{ .reg .u64 t; cvta.to.shared.u64 t, %1; cvt.u32.u64 %0, t; }" : "=r"(a) : "l"(p));
    return a;
}
// 128-byte rows (64 fp16), 8 chunks of 16B; per-row bijective chunk permutation
__device__ __forceinline__ uint32_t swz(int row, int ch) {
    return (uint32_t)(row * 128 + ((ch ^ (row & 7)) << 4));
}
__device__ __forceinline__ void ldsm4(uint32_t* r, uint32_t addr) {
    asm volatile("ldmatrix.sync.aligned.m8n8.x4.shared.b16 {%0,%1,%2,%3}, [%4];"
                 : "=r"(r[0]), "=r"(r[1]), "=r"(r[2]), "=r"(r[3]) : "r"(addr));
}
__device__ __forceinline__ void cp16(uint32_t dst, const void* src) {
    asm volatile("cp.async.cg.shared.global [%0], [%1], 16;" :: "r"(dst), "l"(src));
}
__device__ __forceinline__ void mma_fp16(float* c, const uint32_t* a, const uint32_t* b) {
    asm volatile(
        "mma.sync.aligned.m16n8k16.row.col.f32.f16.f16.f32 "
        "{%0,%1,%2,%3}, {%4,%5,%6,%7}, {%8,%9}, {%0,%1,%2,%3};"
        : "+f"(c[0]), "+f"(c[1]), "+f"(c[2]), "+f"(c[3])
        : "r"(a[0]), "r"(a[1]), "r"(a[2]), "r"(a[3]), "r"(b[0]), "r"(b[1]));
}
__device__ __forceinline__ uint32_t pack2h(float a, float b) {
    const __half2 h = __floats2half2_rn(a, b);
    return *(const uint32_t*)&h;
}

__device__ __forceinline__ int dop_index(int j) {
    if (j == N_DOP - 1) return UNITS - 1;
    const double step = 510.0 / 127.0;
    return (int)((double)j * step + 1.0);
}

// ---------------------------------------------------------------------------
// prep_a: per-dop-neuron |w-old| sums; also re-zeroes tile counters each call
// ---------------------------------------------------------------------------
__global__ void prep_a_kernel(const float* __restrict__ w,
                              const float* __restrict__ dop_old,
                              const float* __restrict__ indicator,
                              const int* __restrict__ bc_raw) {
    __shared__ float red[8];
    const int j = blockIdx.x;
    const int d = dop_index(j);
    const int tid = threadIdx.x, lane = tid & 31, wid = tid >> 5;

    // zero 4 tile counters per block (128 blocks x 4 = 512)
    if (tid < 4) g_tilecnt[j * 4 + tid] = 0;

    float s = 0.0f;
    for (int i = tid; i < N_INPUT; i += blockDim.x)
        s += fabsf(w[i * UNITS + d] - dop_old[i * UNITS + d]);
    #pragma unroll
    for (int o = 16; o > 0; o >>= 1) s += __shfl_xor_sync(0xffffffffu, s, o);
    if (lane == 0) red[wid] = s;
    __syncthreads();
    if (tid == 0) {
        float t = 0.0f;
        #pragma unroll
        for (int q = 0; q < 8; q++) t += red[q];
        float bc;
        {
            int iv = bc_raw[0];
            if (iv >= -1000000 && iv <= 1000000) bc = (float)iv;
            else bc = __int_as_float(iv);
        }
        const float diff = t * (1.0f / (float)N_INPUT);
        g_fac[j] = 1.0f + 10.0f * diff;
        g_act[j] = (diff > 0.0f) && ((bc - indicator[j]) > 2.0f);
    }
}

// ---------------------------------------------------------------------------
// prep_b: build g_mult (two-phase; validated R3/R9-R14)
// ---------------------------------------------------------------------------
__global__ void prep_b_kernel() {
    __shared__ float s_mult[UNITS];
    __shared__ unsigned char s_isdop[UNITS];
    const int tid = threadIdx.x;
    s_mult[tid] = 1.0f;
    s_isdop[tid] = 0;
    __syncthreads();
    if (tid < N_DOP) s_isdop[dop_index(tid)] = 1;
    __syncthreads();
    if (tid < N_DOP) {
        const int d = dop_index(tid);
        const int c = d - 1;
        if (g_act[tid] && !s_isdop[c]) s_mult[c] *= g_fac[tid];
    }
    __syncthreads();
    if (tid < N_DOP) {
        const int d = dop_index(tid);
        const int c = (d + 1) & (UNITS - 1);
        const bool rightok = (d + 1 >= UNITS) ? true : (!s_isdop[d + 1]);
        if (g_act[tid] && rightok) s_mult[c] *= g_fac[tid];
    }
    __syncthreads();
    g_mult[tid] = s_mult[tid];
}

// ---------------------------------------------------------------------------
// prep2: coalesced transpose+scale+fp16 (validated R9-R14)
// ---------------------------------------------------------------------------
__global__ void prep2_kernel(const float* __restrict__ w) {
    __shared__ float tile[32][33];
    const int tx = threadIdx.x, ty = threadIdx.y;
    const int n0 = blockIdx.x * 32, k0 = blockIdx.y * 32;
    tile[ty][tx] = w[(size_t)(k0 + ty) * UNITS + n0 + tx];
    __syncthreads();
    const float m = g_mult[n0 + ty];
    g_w16[(size_t)(n0 + ty) * N_INPUT + k0 + tx] = __float2half_rn(tile[tx][ty] * m);
}

// load one k16-step's fragments (2 ldsm4 A + 4 ldsm4 B)
#define LOAD_FRAGS(ksv, AH, BH) do {                                           \
    _Pragma("unroll")                                                          \
    for (int mt = 0; mt < 2; mt++) {                                           \
        const int row = warp_m * 32 + mt * 16 + (lane & 15);                   \
        const int ch  = (ksv) * 2 + (lane >> 4);                               \
        ldsm4(AH[mt], cb + OFF_A + swz(row, ch));                              \
    }                                                                          \
    _Pragma("unroll")                                                          \
    for (int np = 0; np < 4; np++) {                                           \
        const int g = lane >> 3;                                               \
        const int row = warp_n * 64 + (np * 2 + (g >> 1)) * 8 + (lane & 7);    \
        const int ch  = (ksv) * 2 + (g & 1);                                   \
        uint32_t r[4];                                                         \
        ldsm4(r, cb + OFF_B + swz(row, ch));                                   \
        BH[np * 2 + 0][0] = r[0]; BH[np * 2 + 0][1] = r[1];                    \
        BH[np * 2 + 1][0] = r[2]; BH[np * 2 + 1][1] = r[3];                    \
    }                                                                          \
} while (0)

// ---------------------------------------------------------------------------
// mega: blocks [0, xb) convert X fp32->fp16 and publish per-tile flags;
// blocks [xb, ...) run the R14 GEMM, gated on their M-tile's flag.
// xconv blocks precede all GEMM blocks in issue order -> no deadlock.
// ---------------------------------------------------------------------------
__global__ __launch_bounds__(THREADS, 2)
void mega_kernel(const float* __restrict__ x, int xb,
                 const float* __restrict__ bias, float* __restrict__ C) {
    const int tid = threadIdx.x, lane = tid & 31, wid = tid >> 5;

    if ((int)blockIdx.x < xb) {
        // ---- xconv: 256 groups of 8 elems = 2048 elems = 4 rows ----
        const int i = blockIdx.x * THREADS + tid;
        const float4 v0 = ((const float4*)x)[2 * i];
        const float4 v1 = ((const float4*)x)[2 * i + 1];
        ((uint4*)g_x16)[i] = make_uint4(
            pack2h(v0.x, v0.y), pack2h(v0.z, v0.w),
            pack2h(v1.x, v1.y), pack2h(v1.z, v1.w));
        __threadfence();
        __syncthreads();
        if (tid == 0) atomicAdd(&g_tilecnt[blockIdx.x >> 5], 1);
        return;
    }

    // ---- GEMM ----
    extern __shared__ char dsm[];
    __shared__ float sbias[BN];

    const int idx = (int)blockIdx.x - xb;
    const int bx = idx & 3;          // N tile (UNITS/BN = 4)
    const int by = idx >> 2;         // M tile
    const uint32_t raw = smem_u32(dsm);
    const uint32_t base = (raw + 127u) & ~127u;

    if (tid < BN) sbias[tid] = bias[bx * BN + tid];

    // gate on this M-tile's conversion (32 xconv blocks per tile)
    if (tid == 0) {
        int v;
        do {
            asm volatile("ld.acquire.gpu.global.b32 %0, [%1];"
                         : "=r"(v) : "l"(&g_tilecnt[by]) : "memory");
        } while (v < 32);
    }
    __syncthreads();

    const int warp_m = wid & 3;      // 4 warps in M (32 rows each)
    const int warp_n = wid >> 2;     // 2 warps in N (64 cols each)

    const __half* gA = g_x16 + (size_t)by * BM * N_INPUT;
    const __half* gB = g_w16 + (size_t)bx * BN * N_INPUT;

    float acc[2][8][4];
    #pragma unroll
    for (int mt = 0; mt < 2; mt++)
        #pragma unroll
        for (int nt = 0; nt < 8; nt++)
            #pragma unroll
            for (int q = 0; q < 4; q++) acc[mt][nt][q] = 0.0f;

    // ---- prologue: issue stages 0 and 1 ----
    #pragma unroll
    for (int s = 0; s < 2; s++) {
        const uint32_t bb = base + s * BUF_STRIDE;
        #pragma unroll
        for (int i = 0; i < 4; i++) {
            const int li = tid + i * 256;
            const int row = li >> 3, ch = li & 7;
            const size_t go = (size_t)row * N_INPUT + s * BK + ch * 8;
            const uint32_t so = swz(row, ch);
            cp16(bb + OFF_A + so, gA + go);
            cp16(bb + OFF_B + so, gB + go);
        }
        asm volatile("cp.async.commit_group;" ::: "memory");
    }

    int bufidx = 0;
    for (int s = 0; s < KSTAGES; s++) {
        if (s < KSTAGES - 2) {
            asm volatile("cp.async.wait_group 1;" ::: "memory");
        } else {
            asm volatile("cp.async.wait_group 0;" ::: "memory");
        }
        __syncthreads();

        if (s + 2 < KSTAGES) {
            int pi = bufidx + 2; if (pi >= NBUF) pi -= NBUF;
            const uint32_t bb = base + pi * BUF_STRIDE;
            #pragma unroll
            for (int i = 0; i < 4; i++) {
                const int li = tid + i * 256;
                const int row = li >> 3, ch = li & 7;
                const size_t go = (size_t)row * N_INPUT + (s + 2) * BK + ch * 8;
                const uint32_t so = swz(row, ch);
                cp16(bb + OFF_A + so, gA + go);
                cp16(bb + OFF_B + so, gB + go);
            }
            asm volatile("cp.async.commit_group;" ::: "memory");
        }

        const uint32_t cb = base + bufidx * BUF_STRIDE;
        uint32_t ah[2][2][4], bh[2][8][2];
        LOAD_FRAGS(0, ah[0], bh[0]);
        #pragma unroll
        for (int ks = 0; ks < 4; ks++) {
            const int cur = ks & 1, nxt = cur ^ 1;
            if (ks < 3) {
                LOAD_FRAGS(ks + 1, ah[nxt], bh[nxt]);
            }
            #pragma unroll
            for (int mt = 0; mt < 2; mt++)
                #pragma unroll
                for (int nt = 0; nt < 8; nt++)
                    mma_fp16(acc[mt][nt], ah[cur][mt], bh[cur][nt]);
        }

        bufidx++; if (bufidx >= NBUF) bufidx -= NBUF;
    }

    // ---- epilogue: bias + relu, float2 stores ----
    const int gq = lane >> 2, tq = lane & 3;
    #pragma unroll
    for (int mt = 0; mt < 2; mt++) {
        const int r0 = warp_m * 32 + mt * 16 + gq;
        float* crow0 = C + ((size_t)by * BM + r0) * UNITS + bx * BN;
        float* crow1 = crow0 + 8 * UNITS;
        #pragma unroll
        for (int nt = 0; nt < 8; nt++) {
            const int col = warp_n * 64 + nt * 8 + tq * 2;
            float2 o0, o1;
            o0.x = fmaxf(acc[mt][nt][0] + sbias[col], 0.0f);
            o0.y = fmaxf(acc[mt][nt][1] + sbias[col + 1], 0.0f);
            o1.x = fmaxf(acc[mt][nt][2] + sbias[col], 0.0f);
            o1.y = fmaxf(acc[mt][nt][3] + sbias[col + 1], 0.0f);
            *(float2*)(crow0 + col) = o0;
            *(float2*)(crow1 + col) = o1;
        }
    }
}

extern "C" void kernel_launch(void* const* d_in, const int* in_sizes, int n_in,
                              void* d_out, int out_size) {
    const float* x   = (const float*)d_in[0];
    const float* w   = (const float*)d_in[1];
    const float* b   = (const float*)d_in[2];
    const float* old = (const float*)d_in[3];
    const float* ind = (const float*)d_in[4];
    const int*   bc  = (const int*)d_in[5];

    const int M = in_sizes[0] / N_INPUT;

    cudaFuncSetAttribute(mega_kernel, cudaFuncAttributeMaxDynamicSharedMemorySize, SMEM_DYN);

    prep_a_kernel<<<N_DOP, 256>>>(w, old, ind, bc);
    prep_b_kernel<<<1, UNITS>>>();
    dim3 tgrid(UNITS / 32, N_INPUT / 32);
    prep2_kernel<<<tgrid, dim3(32, 32)>>>(w);

    const int xb = M / 4;                         // xconv blocks (2048 elems each)
    const int gb = (M / BM) * (UNITS / BN);       // gemm blocks
    mega_kernel<<<xb + gb, THREADS, SMEM_DYN>>>(x, xb, b, (float*)d_out);
}

// round 17
// speedup vs baseline: 1.4859x; 1.4859x over previous
#include <cuda_runtime.h>
#include <cuda_fp16.h>
#include <cstdint>

#define UNITS 512
#define N_DOP 128
#define N_INPUT 512
#define MAX_B 65536
#define MAX_TILES (MAX_B / 128)

#define BM 128
#define BN 128
#define BK 64
#define THREADS 256
#define KSTAGES (N_INPUT / BK)   // 8

// dynamic smem: 3-stage ring of {A 16K | B 16K}
#define NBUF 3
#define BUF_STRIDE 32768
#define OFF_A 0
#define OFF_B 16384
#define SMEM_DYN (NBUF * BUF_STRIDE + 128)

__device__ float g_mult[UNITS];
__device__ float g_fac[N_DOP];
__device__ int   g_act[N_DOP];
__device__ int   g_tilecnt[MAX_TILES];
__device__ __half g_w16[UNITS * N_INPUT];          // [n][k] = w[k][n] * mult[n]
__device__ __half g_x16[(size_t)MAX_B * N_INPUT];  // fp16 copy of X

__device__ __forceinline__ uint32_t smem_u32(const void* p) {
    uint32_t a;
    asm("{ .reg .u64 t; cvta.to.shared.u64 t, %1; cvt.u32.u64 %0, t; }" : "=r"(a) : "l"(p));
    return a;
}
// 128-byte rows (64 fp16), 8 chunks of 16B; per-row bijective chunk permutation
__device__ __forceinline__ uint32_t swz(int row, int ch) {
    return (uint32_t)(row * 128 + ((ch ^ (row & 7)) << 4));
}
__device__ __forceinline__ void ldsm4(uint32_t* r, uint32_t addr) {
    asm volatile("ldmatrix.sync.aligned.m8n8.x4.shared.b16 {%0,%1,%2,%3}, [%4];"
                 : "=r"(r[0]), "=r"(r[1]), "=r"(r[2]), "=r"(r[3]) : "r"(addr));
}
__device__ __forceinline__ void cp16(uint32_t dst, const void* src) {
    asm volatile("cp.async.cg.shared.global [%0], [%1], 16;" :: "r"(dst), "l"(src));
}
__device__ __forceinline__ void mma_fp16(float* c, const uint32_t* a, const uint32_t* b) {
    asm volatile(
        "mma.sync.aligned.m16n8k16.row.col.f32.f16.f16.f32 "
        "{%0,%1,%2,%3}, {%4,%5,%6,%7}, {%8,%9}, {%0,%1,%2,%3};"
        : "+f"(c[0]), "+f"(c[1]), "+f"(c[2]), "+f"(c[3])
        : "r"(a[0]), "r"(a[1]), "r"(a[2]), "r"(a[3]), "r"(b[0]), "r"(b[1]));
}
__device__ __forceinline__ uint32_t pack2h(float a, float b) {
    const __half2 h = __floats2half2_rn(a, b);
    return *(const uint32_t*)&h;
}

__device__ __forceinline__ int dop_index(int j) {
    if (j == N_DOP - 1) return UNITS - 1;
    const double step = 510.0 / 127.0;
    return (int)((double)j * step + 1.0);
}

// ---------------------------------------------------------------------------
// prep_a: per-dop-neuron |w-old| sums; re-zeroes tile counters each call
// ---------------------------------------------------------------------------
__global__ void prep_a_kernel(const float* __restrict__ w,
                              const float* __restrict__ dop_old,
                              const float* __restrict__ indicator,
                              const int* __restrict__ bc_raw) {
    __shared__ float red[8];
    const int j = blockIdx.x;
    const int d = dop_index(j);
    const int tid = threadIdx.x, lane = tid & 31, wid = tid >> 5;

    if (tid < 4) g_tilecnt[j * 4 + tid] = 0;   // 128 blocks x 4 = 512 counters

    float s = 0.0f;
    for (int i = tid; i < N_INPUT; i += blockDim.x)
        s += fabsf(w[i * UNITS + d] - dop_old[i * UNITS + d]);
    #pragma unroll
    for (int o = 16; o > 0; o >>= 1) s += __shfl_xor_sync(0xffffffffu, s, o);
    if (lane == 0) red[wid] = s;
    __syncthreads();
    if (tid == 0) {
        float t = 0.0f;
        #pragma unroll
        for (int q = 0; q < 8; q++) t += red[q];
        float bc;
        {
            int iv = bc_raw[0];
            if (iv >= -1000000 && iv <= 1000000) bc = (float)iv;
            else bc = __int_as_float(iv);
        }
        const float diff = t * (1.0f / (float)N_INPUT);
        g_fac[j] = 1.0f + 10.0f * diff;
        g_act[j] = (diff > 0.0f) && ((bc - indicator[j]) > 2.0f);
    }
}

// ---------------------------------------------------------------------------
// prep_b: build g_mult (two-phase; validated R3/R9-R15)
// ---------------------------------------------------------------------------
__global__ void prep_b_kernel() {
    __shared__ float s_mult[UNITS];
    __shared__ unsigned char s_isdop[UNITS];
    const int tid = threadIdx.x;
    s_mult[tid] = 1.0f;
    s_isdop[tid] = 0;
    __syncthreads();
    if (tid < N_DOP) s_isdop[dop_index(tid)] = 1;
    __syncthreads();
    if (tid < N_DOP) {
        const int d = dop_index(tid);
        const int c = d - 1;
        if (g_act[tid] && !s_isdop[c]) s_mult[c] *= g_fac[tid];
    }
    __syncthreads();
    if (tid < N_DOP) {
        const int d = dop_index(tid);
        const int c = (d + 1) & (UNITS - 1);
        const bool rightok = (d + 1 >= UNITS) ? true : (!s_isdop[d + 1]);
        if (g_act[tid] && rightok) s_mult[c] *= g_fac[tid];
    }
    __syncthreads();
    g_mult[tid] = s_mult[tid];
}

// ---------------------------------------------------------------------------
// prep2: coalesced transpose+scale+fp16 (validated R9-R15)
// ---------------------------------------------------------------------------
__global__ void prep2_kernel(const float* __restrict__ w) {
    __shared__ float tile[32][33];
    const int tx = threadIdx.x, ty = threadIdx.y;
    const int n0 = blockIdx.x * 32, k0 = blockIdx.y * 32;
    tile[ty][tx] = w[(size_t)(k0 + ty) * UNITS + n0 + tx];
    __syncthreads();
    const float m = g_mult[n0 + ty];
    g_w16[(size_t)(n0 + ty) * N_INPUT + k0 + tx] = __float2half_rn(tile[tx][ty] * m);
}

// load one k16-step's fragments (2 ldsm4 A + 4 ldsm4 B)
#define LOAD_FRAGS(ksv, AH, BH) do {                                           \
    _Pragma("unroll")                                                          \
    for (int mt = 0; mt < 2; mt++) {                                           \
        const int row = warp_m * 32 + mt * 16 + (lane & 15);                   \
        const int ch  = (ksv) * 2 + (lane >> 4);                               \
        ldsm4(AH[mt], cb + OFF_A + swz(row, ch));                              \
    }                                                                          \
    _Pragma("unroll")                                                          \
    for (int np = 0; np < 4; np++) {                                           \
        const int g = lane >> 3;                                               \
        const int row = warp_n * 64 + (np * 2 + (g >> 1)) * 8 + (lane & 7);    \
        const int ch  = (ksv) * 2 + (g & 1);                                   \
        uint32_t r[4];                                                         \
        ldsm4(r, cb + OFF_B + swz(row, ch));                                   \
        BH[np * 2 + 0][0] = r[0]; BH[np * 2 + 0][1] = r[1];                    \
        BH[np * 2 + 1][0] = r[2]; BH[np * 2 + 1][1] = r[3];                    \
    }                                                                          \
} while (0)

// ---------------------------------------------------------------------------
// GEMM with inline X conversion: each block converts the 32-row slice
// (by, bx) of its M-tile, then waits for its 3 N-siblings (adjacent block
// indices, co-resident) before the R14 GEMM core.
// ---------------------------------------------------------------------------
__global__ __launch_bounds__(THREADS, 2)
void gemm_kernel(const float* __restrict__ x,
                 const float* __restrict__ bias, float* __restrict__ C) {
    extern __shared__ char dsm[];
    __shared__ float sbias[BN];

    const int tid = threadIdx.x, lane = tid & 31, wid = tid >> 5;
    const int bx = (int)blockIdx.x & 3;    // N tile (UNITS/BN = 4)
    const int by = (int)blockIdx.x >> 2;   // M tile
    const uint32_t raw = smem_u32(dsm);
    const uint32_t base = (raw + 127u) & ~127u;

    // ---- convert own 32-row slice of X tile: rows [by*128 + bx*32, +32) ----
    {
        const size_t base8 = ((size_t)by * BM + bx * 32) * (N_INPUT / 8);
        #pragma unroll
        for (int it = 0; it < 8; it++) {
            const size_t i = base8 + tid + it * 256;   // uint4 group index
            const float4 v0 = ((const float4*)x)[2 * i];
            const float4 v1 = ((const float4*)x)[2 * i + 1];
            ((uint4*)g_x16)[i] = make_uint4(
                pack2h(v0.x, v0.y), pack2h(v0.z, v0.w),
                pack2h(v1.x, v1.y), pack2h(v1.z, v1.w));
        }
        __threadfence();
        __syncthreads();
        if (tid == 0) {
            atomicAdd(&g_tilecnt[by], 1);
            int v;
            do {
                asm volatile("ld.acquire.gpu.global.b32 %0, [%1];"
                             : "=r"(v) : "l"(&g_tilecnt[by]) : "memory");
            } while (v < 4);
        }
    }

    if (tid < BN) sbias[tid] = bias[bx * BN + tid];
    __syncthreads();   // all threads see tile-ready + sbias

    const int warp_m = wid & 3;      // 4 warps in M (32 rows each)
    const int warp_n = wid >> 2;     // 2 warps in N (64 cols each)

    const __half* gA = g_x16 + (size_t)by * BM * N_INPUT;
    const __half* gB = g_w16 + (size_t)bx * BN * N_INPUT;

    float acc[2][8][4];
    #pragma unroll
    for (int mt = 0; mt < 2; mt++)
        #pragma unroll
        for (int nt = 0; nt < 8; nt++)
            #pragma unroll
            for (int q = 0; q < 4; q++) acc[mt][nt][q] = 0.0f;

    // ---- prologue: issue stages 0 and 1 ----
    #pragma unroll
    for (int s = 0; s < 2; s++) {
        const uint32_t bb = base + s * BUF_STRIDE;
        #pragma unroll
        for (int i = 0; i < 4; i++) {
            const int li = tid + i * 256;
            const int row = li >> 3, ch = li & 7;
            const size_t go = (size_t)row * N_INPUT + s * BK + ch * 8;
            const uint32_t so = swz(row, ch);
            cp16(bb + OFF_A + so, gA + go);
            cp16(bb + OFF_B + so, gB + go);
        }
        asm volatile("cp.async.commit_group;" ::: "memory");
    }

    int bufidx = 0;
    for (int s = 0; s < KSTAGES; s++) {
        if (s < KSTAGES - 2) {
            asm volatile("cp.async.wait_group 1;" ::: "memory");
        } else {
            asm volatile("cp.async.wait_group 0;" ::: "memory");
        }
        __syncthreads();

        if (s + 2 < KSTAGES) {
            int pi = bufidx + 2; if (pi >= NBUF) pi -= NBUF;
            const uint32_t bb = base + pi * BUF_STRIDE;
            #pragma unroll
            for (int i = 0; i < 4; i++) {
                const int li = tid + i * 256;
                const int row = li >> 3, ch = li & 7;
                const size_t go = (size_t)row * N_INPUT + (s + 2) * BK + ch * 8;
                const uint32_t so = swz(row, ch);
                cp16(bb + OFF_A + so, gA + go);
                cp16(bb + OFF_B + so, gB + go);
            }
            asm volatile("cp.async.commit_group;" ::: "memory");
        }

        const uint32_t cb = base + bufidx * BUF_STRIDE;
        uint32_t ah[2][2][4], bh[2][8][2];
        LOAD_FRAGS(0, ah[0], bh[0]);
        #pragma unroll
        for (int ks = 0; ks < 4; ks++) {
            const int cur = ks & 1, nxt = cur ^ 1;
            if (ks < 3) {
                LOAD_FRAGS(ks + 1, ah[nxt], bh[nxt]);
            }
            #pragma unroll
            for (int mt = 0; mt < 2; mt++)
                #pragma unroll
                for (int nt = 0; nt < 8; nt++)
                    mma_fp16(acc[mt][nt], ah[cur][mt], bh[cur][nt]);
        }

        bufidx++; if (bufidx >= NBUF) bufidx -= NBUF;
    }

    // ---- epilogue: bias + relu, float2 stores ----
    const int gq = lane >> 2, tq = lane & 3;
    #pragma unroll
    for (int mt = 0; mt < 2; mt++) {
        const int r0 = warp_m * 32 + mt * 16 + gq;
        float* crow0 = C + ((size_t)by * BM + r0) * UNITS + bx * BN;
        float* crow1 = crow0 + 8 * UNITS;
        #pragma unroll
        for (int nt = 0; nt < 8; nt++) {
            const int col = warp_n * 64 + nt * 8 + tq * 2;
            float2 o0, o1;
            o0.x = fmaxf(acc[mt][nt][0] + sbias[col], 0.0f);
            o0.y = fmaxf(acc[mt][nt][1] + sbias[col + 1], 0.0f);
            o1.x = fmaxf(acc[mt][nt][2] + sbias[col], 0.0f);
            o1.y = fmaxf(acc[mt][nt][3] + sbias[col + 1], 0.0f);
            *(float2*)(crow0 + col) = o0;
            *(float2*)(crow1 + col) = o1;
        }
    }
}

extern "C" void kernel_launch(void* const* d_in, const int* in_sizes, int n_in,
                              void* d_out, int out_size) {
    const float* x   = (const float*)d_in[0];
    const float* w   = (const float*)d_in[1];
    const float* b   = (const float*)d_in[2];
    const float* old = (const float*)d_in[3];
    const float* ind = (const float*)d_in[4];
    const int*   bc  = (const int*)d_in[5];

    const int M = in_sizes[0] / N_INPUT;

    cudaFuncSetAttribute(gemm_kernel, cudaFuncAttributeMaxDynamicSharedMemorySize, SMEM_DYN);

    prep_a_kernel<<<N_DOP, 256>>>(w, old, ind, bc);
    prep_b_kernel<<<1, UNITS>>>();
    dim3 tgrid(UNITS / 32, N_INPUT / 32);
    prep2_kernel<<<tgrid, dim3(32, 32)>>>(w);

    gemm_kernel<<<(M / BM) * (UNITS / BN), THREADS, SMEM_DYN>>>(x, b, (float*)d_out);
}